// round 15
// baseline (speedup 1.0000x reference)
#include <cuda_runtime.h>
#include <cstdint>

// RandomBitFlip — JAX threefry2x32, partitionable mode, bit-exact.
// R15 = R14 (best, 2050us) + B-side overhead trims:
//  - B kernels: grid-stride while loops, grids sized to E[count] not CAP
//  - exit kernels: early-exit checks every 2 draws (fewer divergent regions)
//  - counters padded to 32B slots
// Draw code + ladder frozen (R6/R9/R12 and R10/R13 measurements).

#define NH 14
#define EXPM  0xFF800000u
#define FRACM 0x007FFFFFu
#define SEEDE 42u
#define SEEDF (42u + 10007u)

#define SDE 4            // dense exp draws in phase A
#define SDF 5            // dense frac draws in phase A

static constexpr uint32_t CAP_E1 = 31000000u;  // exp  alive after 4:  E~29.6M
static constexpr uint32_t CAP_F1 = 36500000u;  // frac alive after 5:  E~34.8M
static constexpr uint32_t CAP_E2 = 9600000u;   // exp  alive after 6:  E~8.87M
static constexpr uint32_t CAP_F2 = 12000000u;  // frac alive after 7:  E~11.1M
static constexpr uint32_t CAP_E3 = 2700000u;   // exp  alive after 8:  E~2.32M
static constexpr uint32_t CAP_F3 = 3400000u;   // frac alive after 9:  E~2.95M

// Expected survivor counts (binomial mean, +~0.3% margin) — used ONLY to size
// grids; while-loops cover any count up to CAP for correctness.
static constexpr uint32_t EXP_E1 = 29720000u;
static constexpr uint32_t EXP_F1 = 34890000u;
static constexpr uint32_t EXP_E2 = 8910000u;
static constexpr uint32_t EXP_F2 = 11170000u;
static constexpr uint32_t EXP_E3 = 2330000u;
static constexpr uint32_t EXP_F3 = 2970000u;

__device__ uint2 g_e1[CAP_E1];
__device__ uint2 g_f1[CAP_F1];
__device__ uint2 g_e2[CAP_E2];
__device__ uint2 g_f2[CAP_F2];
__device__ uint2 g_e3[CAP_E3];
__device__ uint2 g_f3[CAP_F3];
__device__ unsigned int g_cnt[48];  // slot i at g_cnt[i*8]: 0=E1 1=F1 2=E2 3=F2 4=E3 5=F3

// ---------------- compile-time threefry (subkey derivation) -----------------

__host__ __device__ constexpr uint32_t rotl_c(uint32_t v, int r) {
    return (v << r) | (v >> (32 - r));
}

__host__ __device__ constexpr uint64_t tf_c(uint32_t k0, uint32_t k1,
                                            uint32_t x0, uint32_t x1) {
    uint32_t ks2 = k0 ^ k1 ^ 0x1BD11BDAu;
    uint32_t ks[3] = {k0, k1, ks2};
    int R0[4] = {13, 15, 26, 6}, R1[4] = {17, 29, 16, 24};
    x0 += k0; x1 += k1;
    for (int b = 0; b < 5; ++b) {
        for (int r = 0; r < 4; ++r) {
            int rr = (b & 1) ? R1[r] : R0[r];
            x0 += x1; x1 = rotl_c(x1, rr); x1 ^= x0;
        }
        x0 += ks[(b + 1) % 3];
        x1 += ks[(b + 2) % 3] + (uint32_t)(b + 1);
    }
    return (uint64_t)x0 | ((uint64_t)x1 << 32);
}
__host__ __device__ constexpr uint64_t foldin(uint32_t seed, int s) {
    return tf_c(0u, seed, 0u, (uint32_t)s);
}

// ---------------- device draw (FROZEN — measured optimal) -------------------

#define ADD_RR(d, a, b) \
    asm("mad.lo.u32 %0, %1, %2, %3;" : "=r"(d) : "r"(a), "r"(one), "r"(b))
#define ADD_RI(d, a, K) \
    asm("mad.lo.u32 %0, %1, %2, %3;" : "=r"(d) : "r"(one), "n"((int)(K)), "r"(a))

template<uint32_t K0, uint32_t K1>
__device__ __forceinline__ uint32_t tfdraw(uint32_t i, uint32_t one) {
    constexpr uint32_t KS2 = K0 ^ K1 ^ 0x1BD11BDAu;
    uint32_t x0, x1;
    ADD_RI(x1, i, K1);
    ADD_RI(x0, x1, K0);
    x1 = __funnelshift_l(x1, x1, 13) ^ x0;
#define RND(r) { ADD_RR(x0, x1, x0); x1 = __funnelshift_l(x1, x1, (r)) ^ x0; }
    RND(15) RND(26) RND(6)
    ADD_RI(x0, x0, K1);  ADD_RI(x1, x1, KS2 + 1u);
    RND(17) RND(29) RND(16) RND(24)
    ADD_RI(x0, x0, KS2); ADD_RI(x1, x1, K0 + 2u);
    RND(13) RND(15) RND(26) RND(6)
    ADD_RI(x0, x0, K0);  ADD_RI(x1, x1, K1 + 3u);
    RND(17) RND(29) RND(16) RND(24)
    ADD_RI(x0, x0, K1);  ADD_RI(x1, x1, KS2 + 4u);
    RND(13) RND(15) RND(26) RND(6)
    ADD_RI(x0, x0, KS2); ADD_RI(x1, x1, K0 + 5u);
#undef RND
    return x0 ^ x1;
}

// AND-accumulate draws S..SEND-1. CHECKEVERY: early-exit test after every
// CHECKEVERY-th draw from CHECKFROM (0 disables; 2 halves branch regions).
template<uint32_t SEED, uint32_t MASK, int S, int SEND, int CHECKFROM, int CHECKEVERY>
__device__ __forceinline__ void accum(uint32_t i, uint32_t one, uint32_t &a) {
    if constexpr (S < SEND) {
        constexpr uint64_t kk = foldin(SEED, S);
        a &= tfdraw<(uint32_t)(kk & 0xFFFFFFFFu), (uint32_t)(kk >> 32)>(i, one);
        if constexpr (CHECKEVERY > 0 && S >= CHECKFROM &&
                      ((S - CHECKFROM) % CHECKEVERY == (CHECKEVERY - 1)) &&
                      (S + 1 < SEND)) {
            if ((a & MASK) == 0u) return;
        }
        accum<SEED, MASK, S + 1, SEND, CHECKFROM, CHECKEVERY>(i, one, a);
    }
}

// ---------------- compaction helpers ----------------------------------------

__device__ __forceinline__ void push2(bool sE, uint32_t pE,
                                      bool sF, uint32_t pF, uint32_t i) {
    __shared__ unsigned shc[2], shb[2];
    if (threadIdx.x < 2) shc[threadIdx.x] = 0u;
    __syncthreads();
    unsigned lane = threadIdx.x & 31u;
    unsigned mE = __ballot_sync(0xFFFFFFFFu, sE);
    unsigned mF = __ballot_sync(0xFFFFFFFFu, sF);
    unsigned wbE = 0u, wbF = 0u;
    if (lane == 0u) {
        if (mE) wbE = atomicAdd(&shc[0], (unsigned)__popc(mE));
        if (mF) wbF = atomicAdd(&shc[1], (unsigned)__popc(mF));
    }
    wbE = __shfl_sync(0xFFFFFFFFu, wbE, 0);
    wbF = __shfl_sync(0xFFFFFFFFu, wbF, 0);
    __syncthreads();
    if (threadIdx.x < 2) shb[threadIdx.x] = atomicAdd(&g_cnt[threadIdx.x * 8u], shc[threadIdx.x]);
    __syncthreads();
    unsigned lb = (1u << lane) - 1u;
    if (sE) {
        unsigned slot = shb[0] + wbE + (unsigned)__popc(mE & lb);
        if (slot < CAP_E1) g_e1[slot] = make_uint2(i, pE);
    }
    if (sF) {
        unsigned slot = shb[1] + wbF + (unsigned)__popc(mF & lb);
        if (slot < CAP_F1) g_f1[slot] = make_uint2(i, pF);
    }
}

__device__ __forceinline__ void push4(const bool* s, const uint2* e,
                                      uint2* list, unsigned cslot, uint32_t cap) {
    __shared__ unsigned shc, shb;
    if (threadIdx.x == 0) shc = 0u;
    __syncthreads();
    unsigned lane = threadIdx.x & 31u;
    unsigned lb = (1u << lane) - 1u;
    unsigned m[4], pre[4], tot = 0u;
#pragma unroll
    for (int k = 0; k < 4; ++k) {
        m[k] = __ballot_sync(0xFFFFFFFFu, s[k]);
        pre[k] = tot;
        tot += (unsigned)__popc(m[k]);
    }
    unsigned wb = 0u;
    if (lane == 0u && tot) wb = atomicAdd(&shc, tot);
    wb = __shfl_sync(0xFFFFFFFFu, wb, 0);
    __syncthreads();
    if (threadIdx.x == 0) shb = atomicAdd(&g_cnt[cslot * 8u], shc);
    __syncthreads();
    unsigned base = shb + wb;
#pragma unroll
    for (int k = 0; k < 4; ++k) {
        if (s[k]) {
            unsigned slot = base + pre[k] + (unsigned)__popc(m[k] & lb);
            if (slot < cap) list[slot] = e[k];
        }
    }
}

// ---------------- kernels ----------------------------------------------------

__global__ void zero_counters() {
    if (threadIdx.x < 48) g_cnt[threadIdx.x] = 0u;
}

__global__ void __launch_bounds__(256)
phaseA(const float* __restrict__ x, float* __restrict__ out, uint32_t one) {
    uint32_t i = blockIdx.x * 256u + threadIdx.x;   // grid exact: no bounds check
    uint32_t pE = 0xFFFFFFFFu, pF = 0xFFFFFFFFu;
    uint32_t xin = __float_as_uint(x[i]);
    accum<SEEDE, EXPM,  0, SDE, 99, 0>(i, one, pE);
    accum<SEEDF, FRACM, 0, SDF, 99, 0>(i, one, pF);
    reinterpret_cast<uint32_t*>(out)[i] = xin;      // final unless a survivor fixes it
    push2((pE & EXPM) != 0u, pE, (pF & FRACM) != 0u, pF, i);
}

// Mid-level body: dense draws [S0,S1) on list lin, recompact survivors to lout.
// Grid-stride while loop: grid sized to E[count]; covers any cnt <= cap_in.
template<uint32_t SEED, uint32_t MASK, int S0, int S1>
__device__ __forceinline__ void bmid_body4(uint32_t vb, uint32_t nb,
                                           const uint2* __restrict__ lin,
                                           unsigned cin, uint32_t cap_in,
                                           uint2* lout, unsigned cout, uint32_t cap_out,
                                           uint32_t one) {
    uint32_t T = nb * 256u;            // stride between the 4 k-segments
    uint32_t W = 4u * T;               // entries per window
    uint32_t t0 = vb * 256u + threadIdx.x;
    uint32_t cnt = g_cnt[cin * 8u]; if (cnt > cap_in) cnt = cap_in;

#pragma unroll 1
    for (uint32_t wb = 0u; wb < cnt; wb += W) {
        uint2 e[4]; bool v[4];
#pragma unroll
        for (int k = 0; k < 4; ++k) {      // 4 back-to-back LDGs -> MLP=4
            uint32_t t = wb + t0 + (uint32_t)k * T;
            v[k] = (t < cnt);
            e[k] = v[k] ? lin[t] : make_uint2(0u, 0u);
        }
        bool s[4];
#pragma unroll
        for (int k = 0; k < 4; ++k) {
            if (v[k]) accum<SEED, MASK, S0, S1, 99, 0>(e[k].x, one, e[k].y);
            s[k] = v[k] && ((e[k].y & MASK) != 0u);
        }
        push4(s, e, lout, cout, cap_out);
    }
}

// Merged level 1: frac blocks [0, nf), exp blocks [nf, nf+ne).
__global__ void __launch_bounds__(256)
b1a(uint32_t nf, uint32_t ne, uint32_t one) {
    if (blockIdx.x < nf) {
        bmid_body4<SEEDF, FRACM, SDF, SDF + 2>(blockIdx.x, nf,
            g_f1, 1u, CAP_F1, g_f2, 3u, CAP_F2, one);      // s5..6
    } else {
        bmid_body4<SEEDE, EXPM, SDE, SDE + 2>(blockIdx.x - nf, ne,
            g_e1, 0u, CAP_E1, g_e2, 2u, CAP_E2, one);      // s4..5
    }
}

// Merged level 2.
__global__ void __launch_bounds__(256)
b1b(uint32_t nf, uint32_t ne, uint32_t one) {
    if (blockIdx.x < nf) {
        bmid_body4<SEEDF, FRACM, SDF + 2, SDF + 4>(blockIdx.x, nf,
            g_f2, 3u, CAP_F2, g_f3, 5u, CAP_F3, one);      // s7..8
    } else {
        bmid_body4<SEEDE, EXPM, SDE + 2, SDE + 4>(blockIdx.x - nf, ne,
            g_e2, 2u, CAP_E2, g_e3, 4u, CAP_E3, one);      // s6..7
    }
}

// Final frac: finish s9..13 with early exit (every 2); XOR frac bits into out.
__global__ void __launch_bounds__(256)
b2Frac(float* __restrict__ out, uint32_t one) {
    uint32_t T = gridDim.x * 256u, W = 4u * T;
    uint32_t t0 = blockIdx.x * 256u + threadIdx.x;
    uint32_t cnt = g_cnt[5u * 8u]; if (cnt > CAP_F3) cnt = CAP_F3;
    uint32_t* ob = reinterpret_cast<uint32_t*>(out);
#pragma unroll 1
    for (uint32_t wb = 0u; wb < cnt; wb += W) {
        uint2 e[4]; bool v[4];
#pragma unroll
        for (int k = 0; k < 4; ++k) {
            uint32_t t = wb + t0 + (uint32_t)k * T;
            v[k] = (t < cnt);
            e[k] = v[k] ? g_f3[t] : make_uint2(0u, 0u);
        }
#pragma unroll
        for (int k = 0; k < 4; ++k) {
            if (v[k]) {
                uint32_t p = e[k].y;
                accum<SEEDF, FRACM, SDF + 4, NH, SDF + 4, 2>(e[k].x, one, p);
                ob[e[k].x] ^= (p & FRACM);   // never affects finiteness
            }
        }
    }
}

// Final exp (last): finish s8..13 (checks every 2), XOR, finite-zero.
// Must run AFTER b2Frac (shared elements; zeroed values must stay zero).
__global__ void __launch_bounds__(256)
b2Exp(float* __restrict__ out, uint32_t one) {
    uint32_t T = gridDim.x * 256u, W = 4u * T;
    uint32_t t0 = blockIdx.x * 256u + threadIdx.x;
    uint32_t cnt = g_cnt[4u * 8u]; if (cnt > CAP_E3) cnt = CAP_E3;
    uint32_t* ob = reinterpret_cast<uint32_t*>(out);
#pragma unroll 1
    for (uint32_t wb = 0u; wb < cnt; wb += W) {
        uint2 e[4]; bool v[4];
#pragma unroll
        for (int k = 0; k < 4; ++k) {
            uint32_t t = wb + t0 + (uint32_t)k * T;
            v[k] = (t < cnt);
            e[k] = v[k] ? g_e3[t] : make_uint2(0u, 0u);
        }
#pragma unroll
        for (int k = 0; k < 4; ++k) {
            if (v[k]) {
                uint32_t p = e[k].y;
                accum<SEEDE, EXPM, SDE + 4, NH, SDE + 4, 2>(e[k].x, one, p);
                uint32_t u = ob[e[k].x] ^ (p & EXPM);
                // zero_out_invalid: non-finite iff exponent field all ones
                ob[e[k].x] = (((u >> 23) & 0xFFu) == 0xFFu) ? 0u : u;
            }
        }
    }
}

extern "C" void kernel_launch(void* const* d_in, const int* in_sizes, int n_in,
                              void* d_out, int out_size) {
    (void)n_in; (void)in_sizes;
    const float* x = (const float*)d_in[0];
    float* out = (float*)d_out;
    uint32_t n = (uint32_t)out_size;           // 67108864 = 262144 * 256

    // grids sized to EXPECTED counts (while-loops cover up to CAP)
    const uint32_t nF1 = (EXP_F1 + 1023u) / 1024u, nE1 = (EXP_E1 + 1023u) / 1024u;
    const uint32_t nF2 = (EXP_F2 + 1023u) / 1024u, nE2 = (EXP_E2 + 1023u) / 1024u;
    const uint32_t nF3 = (EXP_F3 + 1023u) / 1024u, nE3 = (EXP_E3 + 1023u) / 1024u;

    zero_counters<<<1, 64>>>();
    phaseA<<<n / 256u, 256>>>(x, out, 1u);
    b1a<<<nF1 + nE1, 256>>>(nF1, nE1, 1u);
    b1b<<<nF2 + nE2, 256>>>(nF2, nE2, 1u);
    b2Frac<<<nF3, 256>>>(out, 1u);   // frac XOR first
    b2Exp <<<nE3, 256>>>(out, 1u);   // zero-out last
}